// round 1
// baseline (speedup 1.0000x reference)
#include <cuda_runtime.h>
#include <cstdint>
#include <math.h>

// ---------------- problem constants ----------------
constexpr int NB  = 256;   // batch
constexpr int NIN = 64;    // input dim
constexpr int NH  = 768;   // hidden
constexpr int NL  = 4;     // layers
constexpr int NP  = 8;     // PWL pieces
#define EPSV 1e-5f

typedef unsigned long long u64;

// ---------------- device scratch (allocation-free rule: __device__ globals) ----------------
__device__ float    g_h[NB * NH];         // residual stream
__device__ float    g_hn[NB * NH];        // layernormed activations
__device__ float    g_tropT[NL * NH * NH];// transposed trop_w: [l][i][o]
__device__ unsigned g_wmax_enc[NL];       // order-preserving encoded max of trop_w[l]
__device__ unsigned g_wmin_enc[NL];       // order-preserving encoded min
__device__ float    g_cand_val[NB * NH];  // candidate hn values per row (capacity NH = always safe)
__device__ int      g_cand_idx[NB * NH];  // candidate indices
__device__ int      g_cand_cnt[NB];

// order-preserving float <-> uint map (for atomic float min/max)
__device__ __forceinline__ unsigned f2ord(float f) {
    unsigned u = __float_as_uint(f);
    return (u & 0x80000000u) ? ~u : (u | 0x80000000u);
}
__device__ __forceinline__ float ord2f(unsigned u) {
    return __uint_as_float((u & 0x80000000u) ? (u ^ 0x80000000u) : ~u);
}

// ---------------- packed f32x2 helpers (Blackwell 2x fp32 path) ----------------
__device__ __forceinline__ u64 dup2(float x) {
    u64 r; asm("mov.b64 %0, {%1, %1};" : "=l"(r) : "f"(x)); return r;
}
__device__ __forceinline__ void ffma2(u64 &d, u64 a, u64 b) {
    asm("fma.rn.f32x2 %0, %1, %2, %0;" : "+l"(d) : "l"(a), "l"(b));
}
__device__ __forceinline__ float2 unpack2(u64 v) {
    float2 r; asm("mov.b64 {%0, %1}, %2;" : "=f"(r.x), "=f"(r.y) : "l"(v)); return r;
}

__device__ __forceinline__ float sigmoidf_(float x) { return 1.0f / (1.0f + __expf(-x)); }

// ---------------- kernel 0: init min/max encodings ----------------
__global__ void k_init() {
    int t = threadIdx.x;
    if (t < NL) { g_wmax_enc[t] = 0u; g_wmin_enc[t] = 0xFFFFFFFFu; }
}

// ---------------- kernel 1: transpose trop_w + per-layer min/max ----------------
// trop_w is [l][o][i]; we build g_tropT = [l][i][o] so the candidate gather is coalesced over o.
__global__ void k_trop_prep(const float* __restrict__ tw) {
    __shared__ float tile[32][33];
    int l  = blockIdx.z;
    int i0 = blockIdx.x * 32, o0 = blockIdx.y * 32;
    const float* src = tw + (size_t)l * NH * NH;
    float*       dst = g_tropT + (size_t)l * NH * NH;
    float lmax = -1e30f, lmin = 1e30f;
#pragma unroll
    for (int k = 0; k < 32; k += 8) {
        float v = src[(size_t)(o0 + threadIdx.y + k) * NH + (i0 + threadIdx.x)];
        tile[threadIdx.y + k][threadIdx.x] = v;
        lmax = fmaxf(lmax, v); lmin = fminf(lmin, v);
    }
    __syncthreads();
#pragma unroll
    for (int k = 0; k < 32; k += 8)
        dst[(size_t)(i0 + threadIdx.y + k) * NH + (o0 + threadIdx.x)] = tile[threadIdx.x][threadIdx.y + k];

    for (int off = 16; off > 0; off >>= 1) {
        lmax = fmaxf(lmax, __shfl_down_sync(0xffffffffu, lmax, off));
        lmin = fminf(lmin, __shfl_down_sync(0xffffffffu, lmin, off));
    }
    __shared__ float smax[8], smin[8];
    if (threadIdx.x == 0) { smax[threadIdx.y] = lmax; smin[threadIdx.y] = lmin; }
    __syncthreads();
    if (threadIdx.y == 0 && threadIdx.x == 0) {
        float bm = smax[0], bn = smin[0];
        for (int w = 1; w < 8; w++) { bm = fmaxf(bm, smax[w]); bn = fminf(bn, smin[w]); }
        atomicMax(&g_wmax_enc[l], f2ord(bm));
        atomicMin(&g_wmin_enc[l], f2ord(bn));
    }
}

// ---------------- kernel 2: input GEMM  h = x @ w_in + b_in ----------------
__global__ void k_input(const float* __restrict__ x, const float* __restrict__ w_in,
                        const float* __restrict__ b_in) {
    __shared__ float xs[NIN];
    int b = blockIdx.y;
    int t = threadIdx.x;
    if (t < NIN) xs[t] = x[b * NIN + t];
    __syncthreads();
    int o = blockIdx.x * 128 + t;
    float acc = b_in[o];
#pragma unroll 16
    for (int i = 0; i < NIN; i++) acc += xs[i] * w_in[i * NH + o];
    g_h[b * NH + o] = acc;
}

// ---------------- kernel 3: layernorm + tropical candidate extraction ----------------
__global__ void k_ln_cand(const float* __restrict__ ln_g, const float* __restrict__ ln_b, int l) {
    __shared__ float sh[NH];
    __shared__ float r1[8], r2[8];
    __shared__ float bcast[2];
    __shared__ int cnt;
    int b = blockIdx.x, t = threadIdx.x;
    int lane = t & 31, wid = t >> 5;
    float v0 = g_h[b * NH + t], v1 = g_h[b * NH + t + 256], v2 = g_h[b * NH + t + 512];
    float s = v0 + v1 + v2;
    float q = v0 * v0 + v1 * v1 + v2 * v2;
    for (int off = 16; off > 0; off >>= 1) {
        s += __shfl_down_sync(0xffffffffu, s, off);
        q += __shfl_down_sync(0xffffffffu, q, off);
    }
    if (lane == 0) { r1[wid] = s; r2[wid] = q; }
    __syncthreads();
    if (t == 0) {
        float ss = 0.f, qq = 0.f;
        for (int w = 0; w < 8; w++) { ss += r1[w]; qq += r2[w]; }
        float mu  = ss / (float)NH;
        float var = fmaxf(qq / (float)NH - mu * mu, 0.f);
        bcast[0] = mu; bcast[1] = rsqrtf(var + EPSV);
        cnt = 0;
    }
    __syncthreads();
    float mu = bcast[0], inv = bcast[1];
    float m = -1e30f;
    {
        int j = t;
        float hn = (v0 - mu) * inv * ln_g[l * NH + j] + ln_b[l * NH + j];
        sh[j] = hn; g_hn[b * NH + j] = hn; m = fmaxf(m, hn);
        j = t + 256;
        hn = (v1 - mu) * inv * ln_g[l * NH + j] + ln_b[l * NH + j];
        sh[j] = hn; g_hn[b * NH + j] = hn; m = fmaxf(m, hn);
        j = t + 512;
        hn = (v2 - mu) * inv * ln_g[l * NH + j] + ln_b[l * NH + j];
        sh[j] = hn; g_hn[b * NH + j] = hn; m = fmaxf(m, hn);
    }
    for (int off = 16; off > 0; off >>= 1) m = fmaxf(m, __shfl_down_sync(0xffffffffu, m, off));
    if (lane == 0) r1[wid] = m;
    __syncthreads();
    if (t == 0) {
        float mm = r1[0];
        for (int w = 1; w < 8; w++) mm = fmaxf(mm, r1[w]);
        bcast[0] = mm;
    }
    __syncthreads();
    // EXACT pruning: i with hn[i] < rowmax - (Wmax-Wmin) can never win max_i(hn[i]+W[o,i]).
    float spread = ord2f(g_wmax_enc[l]) - ord2f(g_wmin_enc[l]);
    float tau = bcast[0] - spread - 1e-6f;   // tiny pad for rounding safety
#pragma unroll
    for (int k = 0; k < 3; k++) {
        int j = t + k * 256;
        float hv = sh[j];
        if (hv >= tau) {
            int p = atomicAdd(&cnt, 1);      // order nondeterministic; fmax over set is order-independent
            g_cand_val[b * NH + p] = hv;
            g_cand_idx[b * NH + p] = j;
        }
    }
    __syncthreads();
    if (t == 0) g_cand_cnt[b] = cnt;
}

// ---------------- layer epilogue: tropical (candidates) + LF + gelu + gate + residual ----------------
__device__ __forceinline__ void layer_epilogue(
    int r, int oa, float2 cls, float2 gate, int l,
    const float* __restrict__ cls_b,  const float* __restrict__ gate_b,
    const float* __restrict__ trop_b,
    const float* __restrict__ lf_amax, const float* __restrict__ lf_bmax,
    const float* __restrict__ lf_amin, const float* __restrict__ lf_bmin,
    const float* __restrict__ lf_alpha)
{
    int cnt = g_cand_cnt[r];
    const float* tT = g_tropT + (size_t)l * NH * NH;
    const float* cv = g_cand_val + r * NH;
    const int*   ci = g_cand_idx + r * NH;
    float t0 = -1e30f, t1 = -1e30f;
    for (int c = 0; c < cnt; c++) {
        float v = cv[c]; int ic = ci[c];
        float2 tw = *(const float2*)(tT + (size_t)ic * NH + oa);
        t0 = fmaxf(t0, v + tw.x);
        t1 = fmaxf(t1, v + tw.y);
    }
#pragma unroll
    for (int k = 0; k < 2; k++) {
        int o = oa + k;
        float tt = (k ? t1 : t0) + trop_b[l * NH + o];
        const float4* AM = (const float4*)(lf_amax + ((size_t)l * NH + o) * NP);
        const float4* BM = (const float4*)(lf_bmax + ((size_t)l * NH + o) * NP);
        const float4* AN = (const float4*)(lf_amin + ((size_t)l * NH + o) * NP);
        const float4* BMN = (const float4*)(lf_bmin + ((size_t)l * NH + o) * NP);
        float fmx = -1e30f, fmn = 1e30f;
#pragma unroll
        for (int q = 0; q < 2; q++) {
            float4 am = AM[q], bm = BM[q], an = AN[q], bn = BMN[q];
            fmx = fmaxf(fmx, fmaxf(fmaxf(tt * am.x + bm.x, tt * am.y + bm.y),
                                   fmaxf(tt * am.z + bm.z, tt * am.w + bm.w)));
            fmn = fminf(fmn, fminf(fminf(tt * an.x + bn.x, tt * an.y + bn.y),
                                   fminf(tt * an.z + bn.z, tt * an.w + bn.w)));
        }
        float a = sigmoidf_(lf_alpha[l * NH + o]);
        float trop_out = a * fmx + (1.0f - a) * fmn;
        float cvv = (k ? cls.y : cls.x) + cls_b[l * NH + o];
        float cls_out = 0.5f * cvv * (1.0f + erff(cvv * 0.70710678118654752f));  // exact gelu
        float gvv = (k ? gate.y : gate.x) + gate_b[l * NH + o];
        float gg = sigmoidf_(gvv);
        float res = g_h[r * NH + o];
        g_h[r * NH + o] = res + gg * trop_out + (1.0f - gg) * cls_out;
    }
}

// ---------------- kernel 4: fused layer main (2 dense GEMMs via FFMA2 + epilogue) ----------------
// grid (NH/32, NB/16) = (24,16) = 384 blocks; block 128 threads; 48KB dynamic smem hn tile.
// thread = 2 rows x 1 o-pair x {cls,gate}: packed f32x2 accumulators, weight float2 load IS the packed operand.
__global__ void k_layer(
    const float* __restrict__ cls_w,  const float* __restrict__ cls_b,
    const float* __restrict__ gate_w, const float* __restrict__ gate_b,
    const float* __restrict__ trop_b,
    const float* __restrict__ lf_amax, const float* __restrict__ lf_bmax,
    const float* __restrict__ lf_amin, const float* __restrict__ lf_bmin,
    const float* __restrict__ lf_alpha, int l)
{
    extern __shared__ float hn_s[];                 // [16][768]
    int r0 = blockIdx.y * 16, o0 = blockIdx.x * 32;
    int t = threadIdx.x;
    for (int idx = t; idx < 16 * NH; idx += 128)
        hn_s[idx] = g_hn[r0 * NH + idx];            // (r0+lr)*NH + i == r0*NH + idx
    __syncthreads();

    int og = t & 15, rg = t >> 4;                   // 16 o-pairs x 8 row-pairs
    int oa = o0 + og * 2;
    int lrA = rg * 2;
    const float* wcp = cls_w  + (size_t)l * NH * NH + oa;
    const float* wgp = gate_w + (size_t)l * NH * NH + oa;
    const float* hA = hn_s + lrA * NH;
    const float* hB = hA + NH;

    u64 aC0 = 0, aC1 = 0, aG0 = 0, aG1 = 0;
#pragma unroll 4
    for (int i = 0; i < NH; i++) {
        u64 wc = *(const u64*)(wcp + (size_t)i * NH);
        u64 wg = *(const u64*)(wgp + (size_t)i * NH);
        u64 d0 = dup2(hA[i]);
        u64 d1 = dup2(hB[i]);
        ffma2(aC0, d0, wc); ffma2(aG0, d0, wg);
        ffma2(aC1, d1, wc); ffma2(aG1, d1, wg);
    }
    float2 c0 = unpack2(aC0), c1 = unpack2(aC1);
    float2 gg0 = unpack2(aG0), gg1 = unpack2(aG1);

    layer_epilogue(r0 + lrA,     oa, c0, gg0, l, cls_b, gate_b, trop_b,
                   lf_amax, lf_bmax, lf_amin, lf_bmin, lf_alpha);
    layer_epilogue(r0 + lrA + 1, oa, c1, gg1, l, cls_b, gate_b, trop_b,
                   lf_amax, lf_bmax, lf_amin, lf_bmin, lf_alpha);
}

// ---------------- kernel 5: final layernorm + head ----------------
__global__ void k_final(const float* __restrict__ out_g, const float* __restrict__ out_b,
                        const float* __restrict__ head_w, const float* __restrict__ head_b,
                        float* __restrict__ out)
{
    __shared__ float r1[8], r2[8];
    __shared__ float bc[2];
    int b = blockIdx.x, t = threadIdx.x, lane = t & 31, wid = t >> 5;
    float v0 = g_h[b * NH + t], v1 = g_h[b * NH + t + 256], v2 = g_h[b * NH + t + 512];
    float s = v0 + v1 + v2;
    float q = v0 * v0 + v1 * v1 + v2 * v2;
    for (int off = 16; off > 0; off >>= 1) {
        s += __shfl_down_sync(0xffffffffu, s, off);
        q += __shfl_down_sync(0xffffffffu, q, off);
    }
    if (lane == 0) { r1[wid] = s; r2[wid] = q; }
    __syncthreads();
    if (t == 0) {
        float ss = 0.f, qq = 0.f;
        for (int w = 0; w < 8; w++) { ss += r1[w]; qq += r2[w]; }
        float mu  = ss / (float)NH;
        float var = fmaxf(qq / (float)NH - mu * mu, 0.f);
        bc[0] = mu; bc[1] = rsqrtf(var + EPSV);
    }
    __syncthreads();
    float mu = bc[0], inv = bc[1];
    float d = ((v0 - mu) * inv * out_g[t]       + out_b[t])       * head_w[t]
            + ((v1 - mu) * inv * out_g[t + 256] + out_b[t + 256]) * head_w[t + 256]
            + ((v2 - mu) * inv * out_g[t + 512] + out_b[t + 512]) * head_w[t + 512];
    for (int off = 16; off > 0; off >>= 1) d += __shfl_down_sync(0xffffffffu, d, off);
    __syncthreads();
    if (lane == 0) r1[wid] = d;
    __syncthreads();
    if (t == 0) {
        float dd = 0.f;
        for (int w = 0; w < 8; w++) dd += r1[w];
        out[b] = dd + head_b[0];
    }
}

// ---------------- launch ----------------
extern "C" void kernel_launch(void* const* d_in, const int* in_sizes, int n_in,
                              void* d_out, int out_size) {
    const float* x        = (const float*)d_in[0];
    const float* w_in     = (const float*)d_in[1];
    const float* b_in     = (const float*)d_in[2];
    const float* ln_g     = (const float*)d_in[3];
    const float* ln_b     = (const float*)d_in[4];
    const float* trop_w   = (const float*)d_in[5];
    const float* trop_b   = (const float*)d_in[6];
    const float* lf_amax  = (const float*)d_in[7];
    const float* lf_bmax  = (const float*)d_in[8];
    const float* lf_amin  = (const float*)d_in[9];
    const float* lf_bmin  = (const float*)d_in[10];
    const float* lf_alpha = (const float*)d_in[11];
    const float* gate_w   = (const float*)d_in[12];
    const float* gate_b   = (const float*)d_in[13];
    const float* cls_w    = (const float*)d_in[14];
    const float* cls_b    = (const float*)d_in[15];
    const float* out_g    = (const float*)d_in[16];
    const float* out_b    = (const float*)d_in[17];
    const float* head_w   = (const float*)d_in[18];
    const float* head_b   = (const float*)d_in[19];
    float* out = (float*)d_out;

    cudaFuncSetAttribute(k_layer, cudaFuncAttributeMaxDynamicSharedMemorySize, 16 * NH * 4);

    k_init<<<1, 32>>>();
    k_trop_prep<<<dim3(NH / 32, NH / 32, NL), dim3(32, 8)>>>(trop_w);
    k_input<<<dim3(NH / 128, NB), 128>>>(x, w_in, b_in);
    for (int l = 0; l < NL; l++) {
        k_ln_cand<<<NB, 256>>>(ln_g, ln_b, l);
        k_layer<<<dim3(NH / 32, NB / 16), 128, 16 * NH * 4>>>(
            cls_w, cls_b, gate_w, gate_b, trop_b,
            lf_amax, lf_bmax, lf_amin, lf_bmin, lf_alpha, l);
    }
    k_final<<<NB, 256>>>(out_g, out_b, head_w, head_b, out);
}

// round 2
// speedup vs baseline: 1.6782x; 1.6782x over previous
#include <cuda_runtime.h>
#include <cstdint>
#include <math.h>

// ---------------- problem constants ----------------
constexpr int NB  = 256;   // batch
constexpr int NIN = 64;    // input dim
constexpr int NH  = 768;   // hidden
constexpr int NL  = 4;     // layers
constexpr int NP  = 8;     // PWL pieces
// GEMM tiling
constexpr int KS  = 8;          // K splits
constexpr int KT  = NH / KS;    // 96 k per block
constexpr int RT  = 32;         // rows per block
constexpr int CT  = 64;         // cols per block
#define EPSV 1e-5f

typedef unsigned long long u64;

// ---------------- device scratch ----------------
__device__ float    g_h[NB * NH];          // residual stream
__device__ float    g_hn[NB * NH];         // layernormed activations
__device__ float    g_tropT[NL * NH * NH]; // transposed trop_w: [l][i][o]
__device__ float    g_part[2 * KS * NB * NH]; // GEMM partials [mat][ks][row][o]
__device__ unsigned g_wmax_enc[NL];
__device__ unsigned g_wmin_enc[NL];
__device__ float    g_cand_val[NB * NH];
__device__ int      g_cand_idx[NB * NH];
__device__ int      g_cand_cnt[NB];

// order-preserving float <-> uint map
__device__ __forceinline__ unsigned f2ord(float f) {
    unsigned u = __float_as_uint(f);
    return (u & 0x80000000u) ? ~u : (u | 0x80000000u);
}
__device__ __forceinline__ float ord2f(unsigned u) {
    return __uint_as_float((u & 0x80000000u) ? (u ^ 0x80000000u) : ~u);
}

// ---------------- packed f32x2 helpers ----------------
__device__ __forceinline__ u64 dup2(float x) {
    u64 r; asm("mov.b64 %0, {%1, %1};" : "=l"(r) : "f"(x)); return r;
}
__device__ __forceinline__ void ffma2(u64 &d, u64 a, u64 b) {
    asm("fma.rn.f32x2 %0, %1, %2, %0;" : "+l"(d) : "l"(a), "l"(b));
}
__device__ __forceinline__ float2 unpack2(u64 v) {
    float2 r; asm("mov.b64 {%0, %1}, %2;" : "=f"(r.x), "=f"(r.y) : "l"(v)); return r;
}
__device__ __forceinline__ float sigmoidf_(float x) { return 1.0f / (1.0f + __expf(-x)); }

// ---------------- kernel 0: init min/max encodings ----------------
__global__ void k_init() {
    int t = threadIdx.x;
    if (t < NL) { g_wmax_enc[t] = 0u; g_wmin_enc[t] = 0xFFFFFFFFu; }
}

// ---------------- kernel 1: transpose trop_w + per-layer min/max ----------------
__global__ void k_trop_prep(const float* __restrict__ tw) {
    __shared__ float tile[32][33];
    int l  = blockIdx.z;
    int i0 = blockIdx.x * 32, o0 = blockIdx.y * 32;
    const float* src = tw + (size_t)l * NH * NH;
    float*       dst = g_tropT + (size_t)l * NH * NH;
    float lmax = -1e30f, lmin = 1e30f;
#pragma unroll
    for (int k = 0; k < 32; k += 8) {
        float v = src[(size_t)(o0 + threadIdx.y + k) * NH + (i0 + threadIdx.x)];
        tile[threadIdx.y + k][threadIdx.x] = v;
        lmax = fmaxf(lmax, v); lmin = fminf(lmin, v);
    }
    __syncthreads();
#pragma unroll
    for (int k = 0; k < 32; k += 8)
        dst[(size_t)(i0 + threadIdx.y + k) * NH + (o0 + threadIdx.x)] = tile[threadIdx.x][threadIdx.y + k];

    for (int off = 16; off > 0; off >>= 1) {
        lmax = fmaxf(lmax, __shfl_down_sync(0xffffffffu, lmax, off));
        lmin = fminf(lmin, __shfl_down_sync(0xffffffffu, lmin, off));
    }
    __shared__ float smax[8], smin[8];
    if (threadIdx.x == 0) { smax[threadIdx.y] = lmax; smin[threadIdx.y] = lmin; }
    __syncthreads();
    if (threadIdx.y == 0 && threadIdx.x == 0) {
        float bm = smax[0], bn = smin[0];
        for (int w = 1; w < 8; w++) { bm = fmaxf(bm, smax[w]); bn = fminf(bn, smin[w]); }
        atomicMax(&g_wmax_enc[l], f2ord(bm));
        atomicMin(&g_wmin_enc[l], f2ord(bn));
    }
}

// ---------------- shared block routine: LayerNorm + candidate extraction ----------------
// Block = one row, 256 threads, each owns j = t, t+256, t+512.
// Writes g_hn, g_cand_* for layer lc. EXACT pruning: i can win max_i(hn[i]+W[o,i])
// only if hn[i] >= rowmax - (Wmax - Wmin).
__device__ __forceinline__ void ln_and_candidates(
    int row, int t, float v0, float v1, float v2,
    const float* __restrict__ ln_g, const float* __restrict__ ln_b, int lc)
{
    __shared__ float r1[8], r2[8], bc[2];
    __shared__ int cnt;
    int lane = t & 31, wid = t >> 5;
    float s = v0 + v1 + v2;
    float q = v0 * v0 + v1 * v1 + v2 * v2;
    for (int off = 16; off > 0; off >>= 1) {
        s += __shfl_down_sync(0xffffffffu, s, off);
        q += __shfl_down_sync(0xffffffffu, q, off);
    }
    if (lane == 0) { r1[wid] = s; r2[wid] = q; }
    __syncthreads();
    if (t == 0) {
        float ss = 0.f, qq = 0.f;
        for (int w = 0; w < 8; w++) { ss += r1[w]; qq += r2[w]; }
        float mu  = ss / (float)NH;
        float var = fmaxf(qq / (float)NH - mu * mu, 0.f);
        bc[0] = mu; bc[1] = rsqrtf(var + EPSV);
        cnt = 0;
    }
    __syncthreads();
    float mu = bc[0], inv = bc[1];
    const float* G = ln_g + lc * NH;
    const float* Bv = ln_b + lc * NH;
    float h0 = (v0 - mu) * inv * G[t]       + Bv[t];
    float h1 = (v1 - mu) * inv * G[t + 256] + Bv[t + 256];
    float h2 = (v2 - mu) * inv * G[t + 512] + Bv[t + 512];
    g_hn[row * NH + t]       = h0;
    g_hn[row * NH + t + 256] = h1;
    g_hn[row * NH + t + 512] = h2;
    float m = fmaxf(h0, fmaxf(h1, h2));
    for (int off = 16; off > 0; off >>= 1) m = fmaxf(m, __shfl_down_sync(0xffffffffu, m, off));
    if (lane == 0) r1[wid] = m;
    __syncthreads();
    if (t == 0) {
        float mm = r1[0];
        for (int w = 1; w < 8; w++) mm = fmaxf(mm, r1[w]);
        bc[0] = mm;
    }
    __syncthreads();
    float spread = ord2f(g_wmax_enc[lc]) - ord2f(g_wmin_enc[lc]);
    float tau = bc[0] - spread - 1e-6f;
    if (h0 >= tau) { int p = atomicAdd(&cnt, 1); g_cand_val[row * NH + p] = h0; g_cand_idx[row * NH + p] = t; }
    if (h1 >= tau) { int p = atomicAdd(&cnt, 1); g_cand_val[row * NH + p] = h1; g_cand_idx[row * NH + p] = t + 256; }
    if (h2 >= tau) { int p = atomicAdd(&cnt, 1); g_cand_val[row * NH + p] = h2; g_cand_idx[row * NH + p] = t + 512; }
    __syncthreads();
    if (t == 0) g_cand_cnt[row] = cnt;
}

// ---------------- kernel 2: input GEMM + first LN/candidates (fused) ----------------
__global__ void k_input_ln(const float* __restrict__ x, const float* __restrict__ w_in,
                           const float* __restrict__ b_in,
                           const float* __restrict__ ln_g, const float* __restrict__ ln_b) {
    __shared__ float xs[NIN];
    int row = blockIdx.x, t = threadIdx.x;
    if (t < NIN) xs[t] = x[row * NIN + t];
    __syncthreads();
    float v[3];
#pragma unroll
    for (int k = 0; k < 3; k++) {
        int j = t + k * 256;
        float acc = b_in[j];
#pragma unroll 16
        for (int i = 0; i < NIN; i++) acc += xs[i] * w_in[i * NH + j];
        v[k] = acc;
        g_h[row * NH + j] = acc;
    }
    ln_and_candidates(row, t, v[0], v[1], v[2], ln_g, ln_b, 0);
}

// ---------------- kernel 3: K-split dual GEMM (cls + gate) via FFMA2 ----------------
// grid (NH/CT=12, NB/RT=8, KS=8) = 768 blocks, 128 threads, 24KB smem.
// thread = 4 rows x 4 cols x 2 mats = 16 FFMA2/iter from 2 LDG.128 + 4 LDS.64
// (hn tile stored PRE-DUPLICATED as f32x2 so LDS.64 is directly the packed operand).
__global__ void __launch_bounds__(128) k_gemm(
    const float* __restrict__ cls_w, const float* __restrict__ gate_w, int l)
{
    __shared__ u64 hs[RT * KT];   // 32 rows x 96 i, f32x2-duplicated (24 KB)
    int o0 = blockIdx.x * CT, r0 = blockIdx.y * RT, ks = blockIdx.z, k0 = ks * KT;
    int t = threadIdx.x;
    for (int idx = t; idx < RT * KT; idx += 128) {
        int r = idx / KT, i = idx - r * KT;
        hs[idx] = dup2(g_hn[(r0 + r) * NH + k0 + i]);
    }
    __syncthreads();

    int og = t & 15, rg = t >> 4;        // 16 col-quads x 8 row-quads
    int oc = o0 + og * 4;
    const float* wc = cls_w  + (size_t)l * NH * NH + (size_t)k0 * NH + oc;
    const float* wg = gate_w + (size_t)l * NH * NH + (size_t)k0 * NH + oc;
    const u64* h0 = hs + rg * 4 * KT;

    u64 a[2][4][2];
#pragma unroll
    for (int m = 0; m < 2; m++)
#pragma unroll
        for (int r = 0; r < 4; r++) { a[m][r][0] = 0; a[m][r][1] = 0; }

#pragma unroll 4
    for (int i = 0; i < KT; i++) {
        ulonglong2 wcv = *(const ulonglong2*)(wc + (size_t)i * NH);
        ulonglong2 wgv = *(const ulonglong2*)(wg + (size_t)i * NH);
#pragma unroll
        for (int r = 0; r < 4; r++) {
            u64 d = h0[r * KT + i];
            ffma2(a[0][r][0], d, wcv.x); ffma2(a[0][r][1], d, wcv.y);
            ffma2(a[1][r][0], d, wgv.x); ffma2(a[1][r][1], d, wgv.y);
        }
    }

#pragma unroll
    for (int m = 0; m < 2; m++)
#pragma unroll
        for (int r = 0; r < 4; r++) {
            float2 lo = unpack2(a[m][r][0]), hi = unpack2(a[m][r][1]);
            *(float4*)(g_part + ((size_t)(m * KS + ks) * NB + r0 + rg * 4 + r) * NH + oc)
                = make_float4(lo.x, lo.y, hi.x, hi.y);
        }
}

// ---------------- kernel 4: epilogue (partial-sum + tropical + LF + gelu + gate + residual)
//                  fused with NEXT layer's LN/candidates, or the final LN + head ----------------
__global__ void k_epi(int l,
    const float* __restrict__ cls_b,  const float* __restrict__ gate_b,
    const float* __restrict__ trop_b,
    const float* __restrict__ lf_amax, const float* __restrict__ lf_bmax,
    const float* __restrict__ lf_amin, const float* __restrict__ lf_bmin,
    const float* __restrict__ lf_alpha,
    const float* __restrict__ ln_g,   const float* __restrict__ ln_b,
    const float* __restrict__ out_g,  const float* __restrict__ out_b,
    const float* __restrict__ head_w, const float* __restrict__ head_b,
    float* __restrict__ out)
{
    __shared__ float scv[NH];
    __shared__ int   sci[NH];
    int row = blockIdx.x, t = threadIdx.x;
    int cnt = g_cand_cnt[row];
    for (int c = t; c < cnt; c += 256) {
        scv[c] = g_cand_val[row * NH + c];
        sci[c] = g_cand_idx[row * NH + c];
    }
    __syncthreads();

    const float* tT = g_tropT + (size_t)l * NH * NH;
    float v[3];
#pragma unroll
    for (int k = 0; k < 3; k++) {
        int j = t + k * 256;
        float c = 0.f, g = 0.f;
#pragma unroll
        for (int ks = 0; ks < KS; ks++) {   // fixed-order sum -> deterministic
            c += g_part[((size_t)ks * NB + row) * NH + j];
            g += g_part[((size_t)(KS + ks) * NB + row) * NH + j];
        }
        c += cls_b[l * NH + j];
        g += gate_b[l * NH + j];

        float tm = -1e30f;
        for (int cc = 0; cc < cnt; cc++)
            tm = fmaxf(tm, scv[cc] + tT[(size_t)sci[cc] * NH + j]);
        float tt = tm + trop_b[l * NH + j];

        const float4* AM  = (const float4*)(lf_amax + ((size_t)l * NH + j) * NP);
        const float4* BM  = (const float4*)(lf_bmax + ((size_t)l * NH + j) * NP);
        const float4* AN  = (const float4*)(lf_amin + ((size_t)l * NH + j) * NP);
        const float4* BMN = (const float4*)(lf_bmin + ((size_t)l * NH + j) * NP);
        float fmx = -1e30f, fmn = 1e30f;
#pragma unroll
        for (int q = 0; q < 2; q++) {
            float4 am = AM[q], bm = BM[q], an = AN[q], bn = BMN[q];
            fmx = fmaxf(fmx, fmaxf(fmaxf(tt * am.x + bm.x, tt * am.y + bm.y),
                                   fmaxf(tt * am.z + bm.z, tt * am.w + bm.w)));
            fmn = fminf(fmn, fminf(fminf(tt * an.x + bn.x, tt * an.y + bn.y),
                                   fminf(tt * an.z + bn.z, tt * an.w + bn.w)));
        }
        float a_ = sigmoidf_(lf_alpha[l * NH + j]);
        float trop_out = a_ * fmx + (1.0f - a_) * fmn;
        float cls_out = 0.5f * c * (1.0f + erff(c * 0.70710678118654752f));
        float gg = sigmoidf_(g);
        v[k] = g_h[row * NH + j] + gg * trop_out + (1.0f - gg) * cls_out;
        g_h[row * NH + j] = v[k];
    }
    __syncthreads();

    if (l < NL - 1) {
        ln_and_candidates(row, t, v[0], v[1], v[2], ln_g, ln_b, l + 1);
    } else {
        // final LayerNorm + head
        __shared__ float fr1[8], fr2[8], fbc[2];
        int lane = t & 31, wid = t >> 5;
        float s = v[0] + v[1] + v[2];
        float q = v[0] * v[0] + v[1] * v[1] + v[2] * v[2];
        for (int off = 16; off > 0; off >>= 1) {
            s += __shfl_down_sync(0xffffffffu, s, off);
            q += __shfl_down_sync(0xffffffffu, q, off);
        }
        if (lane == 0) { fr1[wid] = s; fr2[wid] = q; }
        __syncthreads();
        if (t == 0) {
            float ss = 0.f, qq = 0.f;
            for (int w = 0; w < 8; w++) { ss += fr1[w]; qq += fr2[w]; }
            float mu  = ss / (float)NH;
            float var = fmaxf(qq / (float)NH - mu * mu, 0.f);
            fbc[0] = mu; fbc[1] = rsqrtf(var + EPSV);
        }
        __syncthreads();
        float mu = fbc[0], inv = fbc[1];
        float d = ((v[0] - mu) * inv * out_g[t]       + out_b[t])       * head_w[t]
                + ((v[1] - mu) * inv * out_g[t + 256] + out_b[t + 256]) * head_w[t + 256]
                + ((v[2] - mu) * inv * out_g[t + 512] + out_b[t + 512]) * head_w[t + 512];
        for (int off = 16; off > 0; off >>= 1) d += __shfl_down_sync(0xffffffffu, d, off);
        __syncthreads();
        if (lane == 0) fr1[wid] = d;
        __syncthreads();
        if (t == 0) {
            float dd = 0.f;
            for (int w = 0; w < 8; w++) dd += fr1[w];
            out[row] = dd + head_b[0];
        }
    }
}

// ---------------- launch ----------------
extern "C" void kernel_launch(void* const* d_in, const int* in_sizes, int n_in,
                              void* d_out, int out_size) {
    const float* x        = (const float*)d_in[0];
    const float* w_in     = (const float*)d_in[1];
    const float* b_in     = (const float*)d_in[2];
    const float* ln_g     = (const float*)d_in[3];
    const float* ln_b     = (const float*)d_in[4];
    const float* trop_w   = (const float*)d_in[5];
    const float* trop_b   = (const float*)d_in[6];
    const float* lf_amax  = (const float*)d_in[7];
    const float* lf_bmax  = (const float*)d_in[8];
    const float* lf_amin  = (const float*)d_in[9];
    const float* lf_bmin  = (const float*)d_in[10];
    const float* lf_alpha = (const float*)d_in[11];
    const float* gate_w   = (const float*)d_in[12];
    const float* gate_b   = (const float*)d_in[13];
    const float* cls_w    = (const float*)d_in[14];
    const float* cls_b    = (const float*)d_in[15];
    const float* out_g    = (const float*)d_in[16];
    const float* out_b    = (const float*)d_in[17];
    const float* head_w   = (const float*)d_in[18];
    const float* head_b   = (const float*)d_in[19];
    float* out = (float*)d_out;

    k_init<<<1, 32>>>();
    k_trop_prep<<<dim3(NH / 32, NH / 32, NL), dim3(32, 8)>>>(trop_w);
    k_input_ln<<<NB, 256>>>(x, w_in, b_in, ln_g, ln_b);
    for (int l = 0; l < NL; l++) {
        k_gemm<<<dim3(NH / CT, NB / RT, KS), 128>>>(cls_w, gate_w, l);
        k_epi<<<NB, 256>>>(l, cls_b, gate_b, trop_b,
                           lf_amax, lf_bmax, lf_amin, lf_bmin, lf_alpha,
                           ln_g, ln_b, out_g, out_b, head_w, head_b, out);
    }
}